// round 6
// baseline (speedup 1.0000x reference)
#include <cuda_runtime.h>
#include <math.h>

#define Bq 256
#define Tt 128
#define Ff 768
#define HH 256
#define G4 1024
#define H2 512
#define G8 2048
#define NC 16
#define GXR_OFF 33554432

typedef unsigned long long ull;

__device__ __forceinline__ void fma2(ull& d, ull a, ull b) {
    asm("fma.rn.f32x2 %0,%1,%2,%0;" : "+l"(d) : "l"(a), "l"(b));
}
__device__ __forceinline__ ull pk2(float lo, float hi) {
    ull r; asm("mov.b64 %0,{%1,%2};" : "=l"(r) : "f"(lo), "f"(hi)); return r;
}
__device__ __forceinline__ float2 up2(ull v) {
    float2 r; asm("mov.b64 {%0,%1},%2;" : "=f"(r.x), "=f"(r.y) : "l"(v)); return r;
}
__device__ __forceinline__ unsigned cvt_tf32(float v) {
    unsigned r; asm("cvt.rna.tf32.f32 %0, %1;" : "=r"(r) : "f"(v)); return r;
}
__device__ __forceinline__ void mma_tf32(float c[4], const unsigned a[4], const unsigned b[2]) {
    asm("mma.sync.aligned.m16n8k8.row.col.f32.tf32.tf32.f32 "
        "{%0,%1,%2,%3}, {%4,%5,%6,%7}, {%8,%9}, {%0,%1,%2,%3};"
        : "+f"(c[0]), "+f"(c[1]), "+f"(c[2]), "+f"(c[3])
        : "r"(a[0]), "r"(a[1]), "r"(a[2]), "r"(a[3]), "r"(b[0]), "r"(b[1]));
}

__device__ float g_big[67108864];
__device__ float g_hcat[Bq * Tt * H2];
__device__ float g_wpf[HH * G4];
__device__ float g_wpr[HH * G4];
__device__ float g_wps[H2 * G8];
__device__ float2 g_hwd[2][2][Bq][HH];   // word h, duplicated pairs
__device__ float2 g_hsd[2][Bq][H2];      // sentence h, duplicated pairs

__device__ unsigned g_cnt[16 * 32];
__device__ unsigned g_gen[16 * 32];

__device__ __forceinline__ void group_barrier(int gid, unsigned n) {
    __syncthreads();
    if (threadIdx.x == 0) {
        volatile unsigned* genp = &g_gen[gid * 32];
        unsigned gen = *genp;
        __threadfence();
        if (atomicAdd(&g_cnt[gid * 32], 1u) == n - 1u) {
            atomicExch(&g_cnt[gid * 32], 0u);
            __threadfence();
            atomicExch(&g_gen[gid * 32], gen + 1u);
        } else {
            while (*genp == gen) { }
        }
        __threadfence();
    }
    __syncthreads();
}

__global__ void pack_whh(const float* __restrict__ in, float* __restrict__ out, int H) {
    int idx = blockIdx.x * blockDim.x + threadIdx.x;
    if (idx < 4 * H * H) {
        int g = idx & 3;
        int rem = idx >> 2;
        int n = rem % H;
        int k = rem / H;
        out[idx] = in[(size_t)(g * H + n) * H + k];
    }
}

// ---------------- TF32 tensor-core GEMM (now 2 CTA/SM) -------------------------
#define BKK 16
#define SST 136
__global__ void __launch_bounds__(256, 2) gemm_tf32(
    const float* __restrict__ A, const float* __restrict__ W,
    const float* __restrict__ bias, float* __restrict__ C,
    int M, int N, int K)
{
    __shared__ unsigned As[BKK][SST];
    __shared__ unsigned Bs[BKK][SST];
    int tid = threadIdx.x;
    int lane = tid & 31, wid = tid >> 5;
    int wm = wid >> 2, wn = wid & 3;
    int lq = lane >> 2, lr4 = lane & 3;
    const float* Ab = A + (size_t)blockIdx.y * 128 * K;
    const float* Wb = W + (size_t)blockIdx.x * 128 * K;
    int ldr = tid >> 1;
    int ldk = (tid & 1) * 8;

    float acc[4][4][4];
#pragma unroll
    for (int i = 0; i < 4; i++)
#pragma unroll
        for (int j = 0; j < 4; j++)
#pragma unroll
            for (int r = 0; r < 4; r++) acc[i][j][r] = 0.f;

    for (int k0 = 0; k0 < K; k0 += BKK) {
        float4 a0 = *(const float4*)(Ab + (size_t)ldr * K + k0 + ldk);
        float4 a1 = *(const float4*)(Ab + (size_t)ldr * K + k0 + ldk + 4);
        float4 w0 = *(const float4*)(Wb + (size_t)ldr * K + k0 + ldk);
        float4 w1 = *(const float4*)(Wb + (size_t)ldr * K + k0 + ldk + 4);
        As[ldk + 0][ldr] = cvt_tf32(a0.x); As[ldk + 1][ldr] = cvt_tf32(a0.y);
        As[ldk + 2][ldr] = cvt_tf32(a0.z); As[ldk + 3][ldr] = cvt_tf32(a0.w);
        As[ldk + 4][ldr] = cvt_tf32(a1.x); As[ldk + 5][ldr] = cvt_tf32(a1.y);
        As[ldk + 6][ldr] = cvt_tf32(a1.z); As[ldk + 7][ldr] = cvt_tf32(a1.w);
        Bs[ldk + 0][ldr] = cvt_tf32(w0.x); Bs[ldk + 1][ldr] = cvt_tf32(w0.y);
        Bs[ldk + 2][ldr] = cvt_tf32(w0.z); Bs[ldk + 3][ldr] = cvt_tf32(w0.w);
        Bs[ldk + 4][ldr] = cvt_tf32(w1.x); Bs[ldk + 5][ldr] = cvt_tf32(w1.y);
        Bs[ldk + 6][ldr] = cvt_tf32(w1.z); Bs[ldk + 7][ldr] = cvt_tf32(w1.w);
        __syncthreads();
#pragma unroll
        for (int ks = 0; ks < 2; ks++) {
            int kb = ks * 8;
            unsigned af[4][4];
#pragma unroll
            for (int mf = 0; mf < 4; mf++) {
                int row = wm * 64 + mf * 16 + lq;
                af[mf][0] = As[kb + lr4][row];
                af[mf][1] = As[kb + lr4][row + 8];
                af[mf][2] = As[kb + lr4 + 4][row];
                af[mf][3] = As[kb + lr4 + 4][row + 8];
            }
            unsigned bf[4][2];
#pragma unroll
            for (int nf = 0; nf < 4; nf++) {
                int n = wn * 32 + nf * 8 + lq;
                bf[nf][0] = Bs[kb + lr4][n];
                bf[nf][1] = Bs[kb + lr4 + 4][n];
            }
#pragma unroll
            for (int mf = 0; mf < 4; mf++)
#pragma unroll
                for (int nf = 0; nf < 4; nf++)
                    mma_tf32(acc[mf][nf], af[mf], bf[nf]);
        }
        __syncthreads();
    }
#pragma unroll
    for (int nf = 0; nf < 4; nf++) {
        int col0 = blockIdx.x * 128 + wn * 32 + nf * 8 + 2 * lr4;
        float b0v = bias[col0], b1v = bias[col0 + 1];
#pragma unroll
        for (int mf = 0; mf < 4; mf++) {
            int row0 = blockIdx.y * 128 + wm * 64 + mf * 16 + lq;
            float2 o0 = make_float2(acc[mf][nf][0] + b0v, acc[mf][nf][1] + b1v);
            float2 o1 = make_float2(acc[mf][nf][2] + b0v, acc[mf][nf][3] + b1v);
            *(float2*)(C + (size_t)row0 * N + col0) = o0;
            *(float2*)(C + (size_t)(row0 + 8) * N + col0) = o1;
        }
    }
}

__device__ __forceinline__ float sigf(float x) { return 1.f / (1.f + __expf(-x)); }

// ---------------- word BiLSTM scan: smem weights + dup'd h ----------------------
// 128 CTAs: dir(2) x bt(8) x nt(8). CTA = 32b x 32n. Group = 8 CTAs per (dir,bt).
__global__ void __launch_bounds__(256) word_scan_kernel() {
    extern __shared__ __align__(16) float Ws[];      // [256][128] = 128KB
    int cta = blockIdx.x;
    int dir = cta & 1;
    int id = cta >> 1;
    int bt = id >> 3, nt = id & 7;
    int gid = dir * 8 + bt;
    const float* gxp = dir ? (g_big + GXR_OFF) : g_big;
    const float* wp  = dir ? g_wpr : g_wpf;
    int tid = threadIdx.x;
    int lane = tid & 31, wg = tid >> 5;
    int n = nt * 32 + lane;
    int b0 = bt * 32 + wg * 4;

    for (int i = tid; i < 256 * 32; i += 256) {
        int k = i >> 5, j4 = i & 31;
        ((float4*)Ws)[i] = *(const float4*)(wp + (size_t)k * G4 + nt * 128 + j4 * 4);
    }
    float2* hb0 = &g_hwd[dir][0][0][0];
    float2* hb1 = &g_hwd[dir][1][0][0];
    float c_reg[4] = {0.f, 0.f, 0.f, 0.f};
#pragma unroll
    for (int u = 0; u < 4; u++) hb0[(size_t)(b0 + u) * HH + n] = make_float2(0.f, 0.f);
    group_barrier(gid, 8);

    for (int t = 0; t < Tt; t++) {
        int tt = dir ? (Tt - 1 - t) : t;
        const float2* hp = (t & 1) ? hb1 : hb0;
        float2* hn = (t & 1) ? hb0 : hb1;
        ull a01[4], a23[4];
#pragma unroll
        for (int u = 0; u < 4; u++) {
            const float* gp = gxp + ((size_t)(b0 + u) * Tt + tt) * G4 + n;
            a01[u] = pk2(gp[0], gp[HH]);
            a23[u] = pk2(gp[2 * HH], gp[3 * HH]);
        }
        const ull* h0p = (const ull*)(hp + (size_t)b0 * HH);
        const float* wrow = Ws + lane * 4;
#pragma unroll 8
        for (int k = 0; k < HH; k++) {
            ulonglong2 wv = *(const ulonglong2*)(wrow + k * 128);
            ull h0 = h0p[k];
            ull h1 = h0p[HH + k];
            ull h2 = h0p[2 * HH + k];
            ull h3 = h0p[3 * HH + k];
            fma2(a01[0], h0, wv.x); fma2(a23[0], h0, wv.y);
            fma2(a01[1], h1, wv.x); fma2(a23[1], h1, wv.y);
            fma2(a01[2], h2, wv.x); fma2(a23[2], h2, wv.y);
            fma2(a01[3], h3, wv.x); fma2(a23[3], h3, wv.y);
        }
#pragma unroll
        for (int u = 0; u < 4; u++) {
            float2 p01 = up2(a01[u]);
            float2 p23 = up2(a23[u]);
            float ig = sigf(p01.x), fg = sigf(p01.y);
            float gg = tanhf(p23.x), og = sigf(p23.y);
            c_reg[u] = fg * c_reg[u] + ig * gg;
            float h = og * tanhf(c_reg[u]);
            hn[(size_t)(b0 + u) * HH + n] = make_float2(h, h);
            g_hcat[((size_t)(b0 + u) * Tt + tt) * H2 + dir * HH + n] = h;
        }
        if (t < Tt - 1) group_barrier(gid, 8);
    }
}

// ---------------- sentence LSTM scan: smem weights + dup'd h --------------------
// 128 CTAs: bt(4) x nt(32). CTA = 64b x 16n. Group = 32 CTAs per bt.
__global__ void __launch_bounds__(256) sent_scan_kernel() {
    extern __shared__ __align__(16) float Ws[];      // [512][64] = 128KB
    int cta = blockIdx.x;
    int bt = cta >> 5, nt = cta & 31;
    int tid = threadIdx.x;
    int lane = tid & 31, wg = tid >> 5;
    int nl = lane & 15, half = lane >> 4;
    int n = nt * 16 + nl;
    int b0 = bt * 64 + wg * 8 + half * 4;

    for (int i = tid; i < 512 * 16; i += 256) {
        int k = i >> 4, j4 = i & 15;
        ((float4*)Ws)[i] = *(const float4*)(g_wps + (size_t)k * G8 + nt * 64 + j4 * 4);
    }
    float2* hb0 = &g_hsd[0][0][0];
    float2* hb1 = &g_hsd[1][0][0];
    float c_reg[4] = {0.f, 0.f, 0.f, 0.f};
#pragma unroll
    for (int u = 0; u < 4; u++) hb0[(size_t)(b0 + u) * H2 + n] = make_float2(0.f, 0.f);
    group_barrier(bt, 32);

    for (int t = 0; t < Tt; t++) {
        const float2* hp = (t & 1) ? hb1 : hb0;
        float2* hn = (t & 1) ? hb0 : hb1;
        ull a01[4], a23[4];
#pragma unroll
        for (int u = 0; u < 4; u++) {
            const float* gp = g_big + ((size_t)(b0 + u) * Tt + t) * G8 + n;
            a01[u] = pk2(gp[0], gp[H2]);
            a23[u] = pk2(gp[2 * H2], gp[3 * H2]);
        }
        const ull* h0p = (const ull*)(hp + (size_t)b0 * H2);
        const float* wrow = Ws + nl * 4;
#pragma unroll 8
        for (int k = 0; k < H2; k++) {
            ulonglong2 wv = *(const ulonglong2*)(wrow + k * 64);
            ull h0 = h0p[k];
            ull h1 = h0p[H2 + k];
            ull h2 = h0p[2 * H2 + k];
            ull h3 = h0p[3 * H2 + k];
            fma2(a01[0], h0, wv.x); fma2(a23[0], h0, wv.y);
            fma2(a01[1], h1, wv.x); fma2(a23[1], h1, wv.y);
            fma2(a01[2], h2, wv.x); fma2(a23[2], h2, wv.y);
            fma2(a01[3], h3, wv.x); fma2(a23[3], h3, wv.y);
        }
#pragma unroll
        for (int u = 0; u < 4; u++) {
            float2 p01 = up2(a01[u]);
            float2 p23 = up2(a23[u]);
            float ig = sigf(p01.x), fg = sigf(p01.y);
            float gg = tanhf(p23.x), og = sigf(p23.y);
            c_reg[u] = fg * c_reg[u] + ig * gg;
            float h = og * tanhf(c_reg[u]);
            hn[(size_t)(b0 + u) * H2 + n] = make_float2(h, h);  // t=127 -> hb0 = hT
        }
        if (t < Tt - 1) group_barrier(bt, 32);
    }
}

// ---------------- emissions + CRF (single block) ------------------------------
__global__ void __launch_bounds__(256) crf_kernel(
    const int* __restrict__ y,
    const float* __restrict__ lin_w, const float* __restrict__ lin_b,
    const float* __restrict__ cstart, const float* __restrict__ cend,
    const float* __restrict__ ctrans, float* __restrict__ out)
{
    __shared__ float pool[NC * H2];
    __shared__ float e[Bq][NC];
    int tid = threadIdx.x;

    for (int idx = tid; idx < NC * H2 / 4; idx += 256)
        ((float4*)pool)[idx] = ((const float4*)lin_w)[idx];
    __syncthreads();
    {
        const float2* hrow = &g_hsd[0][tid][0];
        float acc[NC];
#pragma unroll
        for (int c = 0; c < NC; c++) acc[c] = lin_b[c];
        for (int k = 0; k < H2; k += 2) {
            float4 v = *(const float4*)(hrow + k);   // {h[k],h[k], h[k+1],h[k+1]}
#pragma unroll
            for (int c = 0; c < NC; c++) {
                const float* wr = pool + c * H2 + k;
                acc[c] += v.x * wr[0] + v.z * wr[1];
            }
        }
#pragma unroll
        for (int c = 0; c < NC; c++) e[tid][c] = acc[c];
    }
    __syncthreads();
    if (tid < NC * NC) pool[tid] = ctrans[tid];
    __syncthreads();
    float* tr = pool;
    float* alpha = pool + 256;
    float* alpha2 = pool + 288;
    if (tid < NC) alpha[tid] = cstart[tid] + e[0][tid];
    __syncthreads();
    if (tid < 32) {
        for (int s = 1; s < Bq; s++) {
            if (tid < NC) {
                int j = tid;
                float m = -1e30f;
#pragma unroll
                for (int i = 0; i < NC; i++) m = fmaxf(m, alpha[i] + tr[i * NC + j]);
                float sum = 0.f;
#pragma unroll
                for (int i = 0; i < NC; i++) sum += expf(alpha[i] + tr[i * NC + j] - m);
                alpha2[j] = m + logf(sum) + e[s][j];
            }
            __syncwarp();
            if (tid < NC) alpha[tid] = alpha2[tid];
            __syncwarp();
        }
    }
    __syncthreads();
    if (tid == 0) {
        int yprev = y[0];
        float num = cstart[yprev] + e[0][yprev];
        for (int s = 1; s < Bq; s++) {
            int ys = y[s];
            num += tr[yprev * NC + ys] + e[s][ys];
            yprev = ys;
        }
        num += cend[yprev];
        float m = -1e30f;
        for (int i = 0; i < NC; i++) m = fmaxf(m, alpha[i] + cend[i]);
        float sum = 0.f;
        for (int i = 0; i < NC; i++) sum += expf(alpha[i] + cend[i] - m);
        out[0] = num - (m + logf(sum));
    }
}

// ---------------- launch ------------------------------------------------------
extern "C" void kernel_launch(void* const* d_in, const int* in_sizes, int n_in,
                              void* d_out, int out_size)
{
    const float* x      = (const float*)d_in[0];
    const int*   y      = (const int*)  d_in[1];
    const float* w_ih_f = (const float*)d_in[3];
    const float* w_hh_f = (const float*)d_in[4];
    const float* b_f    = (const float*)d_in[5];
    const float* w_ih_r = (const float*)d_in[6];
    const float* w_hh_r = (const float*)d_in[7];
    const float* b_r    = (const float*)d_in[8];
    const float* w_ih_s = (const float*)d_in[9];
    const float* w_hh_s = (const float*)d_in[10];
    const float* b_s    = (const float*)d_in[11];
    const float* lin_w  = (const float*)d_in[12];
    const float* lin_b  = (const float*)d_in[13];
    const float* cstart = (const float*)d_in[14];
    const float* cend   = (const float*)d_in[15];
    const float* ctrans = (const float*)d_in[16];
    float* out = (float*)d_out;

    float *gbig, *hcat, *wpf, *wpr, *wps;
    cudaGetSymbolAddress((void**)&gbig, g_big);
    cudaGetSymbolAddress((void**)&hcat, g_hcat);
    cudaGetSymbolAddress((void**)&wpf, g_wpf);
    cudaGetSymbolAddress((void**)&wpr, g_wpr);
    cudaGetSymbolAddress((void**)&wps, g_wps);

    cudaFuncSetAttribute(word_scan_kernel,
                         cudaFuncAttributeMaxDynamicSharedMemorySize, 131072);
    cudaFuncSetAttribute(sent_scan_kernel,
                         cudaFuncAttributeMaxDynamicSharedMemorySize, 131072);

    pack_whh<<<(4 * HH * HH + 255) / 256, 256>>>(w_hh_f, wpf, HH);
    pack_whh<<<(4 * HH * HH + 255) / 256, 256>>>(w_hh_r, wpr, HH);
    pack_whh<<<(4 * H2 * H2 + 255) / 256, 256>>>(w_hh_s, wps, H2);

    dim3 g1(G4 / 128, (Bq * Tt) / 128);
    gemm_tf32<<<g1, 256>>>(x, w_ih_f, b_f, gbig, Bq * Tt, G4, Ff);
    gemm_tf32<<<g1, 256>>>(x, w_ih_r, b_r, gbig + GXR_OFF, Bq * Tt, G4, Ff);

    word_scan_kernel<<<128, 256, 131072>>>();

    dim3 g2(G8 / 128, (Bq * Tt) / 128);
    gemm_tf32<<<g2, 256>>>(hcat, w_ih_s, b_s, gbig, Bq * Tt, G8, H2);

    sent_scan_kernel<<<128, 256, 131072>>>();

    crf_kernel<<<1, 256>>>(y, lin_w, lin_b, cstart, cend, ctrans, out);
}

// round 7
// speedup vs baseline: 1.9955x; 1.9955x over previous
#include <cuda_runtime.h>
#include <math.h>

#define Bq 256
#define Tt 128
#define Ff 768
#define HH 256
#define G4 1024
#define H2 512
#define G8 2048
#define NC 16
#define GXR_OFF 33554432

typedef unsigned long long ull;

__device__ __forceinline__ void fma2(ull& d, ull a, ull b) {
    asm("fma.rn.f32x2 %0,%1,%2,%0;" : "+l"(d) : "l"(a), "l"(b));
}
__device__ __forceinline__ ull pk2(float lo, float hi) {
    ull r; asm("mov.b64 %0,{%1,%2};" : "=l"(r) : "f"(lo), "f"(hi)); return r;
}
__device__ __forceinline__ float2 up2(ull v) {
    float2 r; asm("mov.b64 {%0,%1},%2;" : "=f"(r.x), "=f"(r.y) : "l"(v)); return r;
}
__device__ __forceinline__ unsigned cvt_tf32(float v) {
    unsigned r; asm("cvt.rna.tf32.f32 %0, %1;" : "=r"(r) : "f"(v)); return r;
}
__device__ __forceinline__ void mma_tf32(float c[4], const unsigned a[4], const unsigned b[2]) {
    asm("mma.sync.aligned.m16n8k8.row.col.f32.tf32.tf32.f32 "
        "{%0,%1,%2,%3}, {%4,%5,%6,%7}, {%8,%9}, {%0,%1,%2,%3};"
        : "+f"(c[0]), "+f"(c[1]), "+f"(c[2]), "+f"(c[3])
        : "r"(a[0]), "r"(a[1]), "r"(a[2]), "r"(a[3]), "r"(b[0]), "r"(b[1]));
}

__device__ float g_big[67108864];
__device__ float g_hcat[Bq * Tt * H2];
__device__ float g_wpf[HH * G4];
__device__ float g_wpr[HH * G4];
__device__ float g_wps[H2 * G8];
__device__ float g_hw[2][2][Bq][HH];
__device__ float g_hs[2][Bq][H2];

__device__ unsigned g_cnt[16 * 32];
__device__ unsigned g_gen[16 * 32];

__device__ __forceinline__ void group_barrier(int gid, unsigned n) {
    __syncthreads();
    if (threadIdx.x == 0) {
        volatile unsigned* genp = &g_gen[gid * 32];
        unsigned gen = *genp;
        __threadfence();
        if (atomicAdd(&g_cnt[gid * 32], 1u) == n - 1u) {
            atomicExch(&g_cnt[gid * 32], 0u);
            __threadfence();
            atomicExch(&g_gen[gid * 32], gen + 1u);
        } else {
            while (*genp == gen) { }
        }
        __threadfence();
    }
    __syncthreads();
}

__global__ void pack_whh(const float* __restrict__ in, float* __restrict__ out, int H) {
    int idx = blockIdx.x * blockDim.x + threadIdx.x;
    if (idx < 4 * H * H) {
        int g = idx & 3;
        int rem = idx >> 2;
        int n = rem % H;
        int k = rem / H;
        out[idx] = in[(size_t)(g * H + n) * H + k];
    }
}

// ---------------- TF32 tensor-core GEMM --------------------------------------
#define BKK 16
#define SST 136
__global__ void __launch_bounds__(256, 2) gemm_tf32(
    const float* __restrict__ A, const float* __restrict__ W,
    const float* __restrict__ bias, float* __restrict__ C,
    int M, int N, int K)
{
    __shared__ unsigned As[BKK][SST];
    __shared__ unsigned Bs[BKK][SST];
    int tid = threadIdx.x;
    int lane = tid & 31, wid = tid >> 5;
    int wm = wid >> 2, wn = wid & 3;
    int lq = lane >> 2, lr4 = lane & 3;
    const float* Ab = A + (size_t)blockIdx.y * 128 * K;
    const float* Wb = W + (size_t)blockIdx.x * 128 * K;
    int ldr = tid >> 1;
    int ldk = (tid & 1) * 8;

    float acc[4][4][4];
#pragma unroll
    for (int i = 0; i < 4; i++)
#pragma unroll
        for (int j = 0; j < 4; j++)
#pragma unroll
            for (int r = 0; r < 4; r++) acc[i][j][r] = 0.f;

    for (int k0 = 0; k0 < K; k0 += BKK) {
        float4 a0 = *(const float4*)(Ab + (size_t)ldr * K + k0 + ldk);
        float4 a1 = *(const float4*)(Ab + (size_t)ldr * K + k0 + ldk + 4);
        float4 w0 = *(const float4*)(Wb + (size_t)ldr * K + k0 + ldk);
        float4 w1 = *(const float4*)(Wb + (size_t)ldr * K + k0 + ldk + 4);
        As[ldk + 0][ldr] = cvt_tf32(a0.x); As[ldk + 1][ldr] = cvt_tf32(a0.y);
        As[ldk + 2][ldr] = cvt_tf32(a0.z); As[ldk + 3][ldr] = cvt_tf32(a0.w);
        As[ldk + 4][ldr] = cvt_tf32(a1.x); As[ldk + 5][ldr] = cvt_tf32(a1.y);
        As[ldk + 6][ldr] = cvt_tf32(a1.z); As[ldk + 7][ldr] = cvt_tf32(a1.w);
        Bs[ldk + 0][ldr] = cvt_tf32(w0.x); Bs[ldk + 1][ldr] = cvt_tf32(w0.y);
        Bs[ldk + 2][ldr] = cvt_tf32(w0.z); Bs[ldk + 3][ldr] = cvt_tf32(w0.w);
        Bs[ldk + 4][ldr] = cvt_tf32(w1.x); Bs[ldk + 5][ldr] = cvt_tf32(w1.y);
        Bs[ldk + 6][ldr] = cvt_tf32(w1.z); Bs[ldk + 7][ldr] = cvt_tf32(w1.w);
        __syncthreads();
#pragma unroll
        for (int ks = 0; ks < 2; ks++) {
            int kb = ks * 8;
            unsigned af[4][4];
#pragma unroll
            for (int mf = 0; mf < 4; mf++) {
                int row = wm * 64 + mf * 16 + lq;
                af[mf][0] = As[kb + lr4][row];
                af[mf][1] = As[kb + lr4][row + 8];
                af[mf][2] = As[kb + lr4 + 4][row];
                af[mf][3] = As[kb + lr4 + 4][row + 8];
            }
            unsigned bf[4][2];
#pragma unroll
            for (int nf = 0; nf < 4; nf++) {
                int n = wn * 32 + nf * 8 + lq;
                bf[nf][0] = Bs[kb + lr4][n];
                bf[nf][1] = Bs[kb + lr4 + 4][n];
            }
#pragma unroll
            for (int mf = 0; mf < 4; mf++)
#pragma unroll
                for (int nf = 0; nf < 4; nf++)
                    mma_tf32(acc[mf][nf], af[mf], bf[nf]);
        }
        __syncthreads();
    }
#pragma unroll
    for (int nf = 0; nf < 4; nf++) {
        int col0 = blockIdx.x * 128 + wn * 32 + nf * 8 + 2 * lr4;
        float b0v = bias[col0], b1v = bias[col0 + 1];
#pragma unroll
        for (int mf = 0; mf < 4; mf++) {
            int row0 = blockIdx.y * 128 + wm * 64 + mf * 16 + lq;
            float2 o0 = make_float2(acc[mf][nf][0] + b0v, acc[mf][nf][1] + b1v);
            float2 o1 = make_float2(acc[mf][nf][2] + b0v, acc[mf][nf][3] + b1v);
            *(float2*)(C + (size_t)row0 * N + col0) = o0;
            *(float2*)(C + (size_t)(row0 + 8) * N + col0) = o1;
        }
    }
}

__device__ __forceinline__ float sigf(float x) { return 1.f / (1.f + __expf(-x)); }

// ---------------- word BiLSTM scan: smem weights + smem dup'd h ----------------
// 128 CTAs: dir(2) x bt(8) x nt(8). CTA = 32b x 32n. Group = 8 CTAs per (dir,bt).
// smem: weights 128KB + h dup 64KB = 192KB.
__global__ void __launch_bounds__(256) word_scan_kernel() {
    extern __shared__ __align__(16) float smp[];
    float* Ws = smp;                                  // [256][128]
    float2* Hd = (float2*)(smp + 256 * 128);          // [32][256] dup pairs
    int cta = blockIdx.x;
    int dir = cta & 1;
    int id = cta >> 1;
    int bt = id >> 3, nt = id & 7;
    int gid = dir * 8 + bt;
    const float* gxp = dir ? (g_big + GXR_OFF) : g_big;
    const float* wp  = dir ? g_wpr : g_wpf;
    int tid = threadIdx.x;
    int lane = tid & 31, wg = tid >> 5;
    int n = nt * 32 + lane;
    int b0 = bt * 32 + wg * 4;

    for (int i = tid; i < 256 * 32; i += 256) {
        int k = i >> 5, j4 = i & 31;
        ((float4*)Ws)[i] = *(const float4*)(wp + (size_t)k * G4 + nt * 128 + j4 * 4);
    }
    float* hb0 = &g_hw[dir][0][0][0];
    float* hb1 = &g_hw[dir][1][0][0];
    float c_reg[4] = {0.f, 0.f, 0.f, 0.f};
#pragma unroll
    for (int u = 0; u < 4; u++) hb0[(size_t)(b0 + u) * HH + n] = 0.f;
    group_barrier(gid, 8);

    for (int t = 0; t < Tt; t++) {
        int tt = dir ? (Tt - 1 - t) : t;
        const float* hp = (t & 1) ? hb1 : hb0;
        float* hn = (t & 1) ? hb0 : hb1;

        // stage h (32 rows x 256 k) dup'd into smem
        {
            const float4* hsrc = (const float4*)(hp + (size_t)(bt * 32) * HH);
            float4* hdst = (float4*)Hd;
            for (int idx = tid; idx < 32 * HH / 4; idx += 256) {
                float4 v = hsrc[idx];
                hdst[2 * idx]     = make_float4(v.x, v.x, v.y, v.y);
                hdst[2 * idx + 1] = make_float4(v.z, v.z, v.w, v.w);
            }
        }
        ull a01[4], a23[4];
#pragma unroll
        for (int u = 0; u < 4; u++) {
            const float* gp = gxp + ((size_t)(b0 + u) * Tt + tt) * G4 + n;
            a01[u] = pk2(gp[0], gp[HH]);
            a23[u] = pk2(gp[2 * HH], gp[3 * HH]);
        }
        __syncthreads();

        const ull* hrow = (const ull*)Hd + (size_t)(wg * 4) * HH;
        const float* wrow = Ws + lane * 4;
#pragma unroll 8
        for (int k = 0; k < HH; k++) {
            ulonglong2 wv = *(const ulonglong2*)(wrow + k * 128);
            ull h0 = hrow[k];
            ull h1 = hrow[HH + k];
            ull h2 = hrow[2 * HH + k];
            ull h3 = hrow[3 * HH + k];
            fma2(a01[0], h0, wv.x); fma2(a23[0], h0, wv.y);
            fma2(a01[1], h1, wv.x); fma2(a23[1], h1, wv.y);
            fma2(a01[2], h2, wv.x); fma2(a23[2], h2, wv.y);
            fma2(a01[3], h3, wv.x); fma2(a23[3], h3, wv.y);
        }
#pragma unroll
        for (int u = 0; u < 4; u++) {
            float2 p01 = up2(a01[u]);
            float2 p23 = up2(a23[u]);
            float ig = sigf(p01.x), fg = sigf(p01.y);
            float gg = tanhf(p23.x), og = sigf(p23.y);
            c_reg[u] = fg * c_reg[u] + ig * gg;
            float h = og * tanhf(c_reg[u]);
            hn[(size_t)(b0 + u) * HH + n] = h;
            g_hcat[((size_t)(b0 + u) * Tt + tt) * H2 + dir * HH + n] = h;
        }
        if (t < Tt - 1) group_barrier(gid, 8);
    }
}

// ---------------- sentence LSTM scan: smem weights + chunked smem dup'd h ------
// 128 CTAs: bt(4) x nt(32). CTA = 64b x 16n. Group = 32 CTAs per bt.
// smem: weights 128KB + h chunk 64KB = 192KB. h staged in 4 chunks of 128 k.
__global__ void __launch_bounds__(256) sent_scan_kernel() {
    extern __shared__ __align__(16) float smp[];
    float* Ws = smp;                                  // [512][64]
    float2* Hd = (float2*)(smp + 512 * 64);           // [64][128] dup pairs
    int cta = blockIdx.x;
    int bt = cta >> 5, nt = cta & 31;
    int tid = threadIdx.x;
    int lane = tid & 31, wg = tid >> 5;
    int nl = lane & 15, half = lane >> 4;
    int n = nt * 16 + nl;
    int b0 = bt * 64 + wg * 8 + half * 4;

    for (int i = tid; i < 512 * 16; i += 256) {
        int k = i >> 4, j4 = i & 15;
        ((float4*)Ws)[i] = *(const float4*)(g_wps + (size_t)k * G8 + nt * 64 + j4 * 4);
    }
    float* hb0 = &g_hs[0][0][0];
    float* hb1 = &g_hs[1][0][0];
    float c_reg[4] = {0.f, 0.f, 0.f, 0.f};
#pragma unroll
    for (int u = 0; u < 4; u++) hb0[(size_t)(b0 + u) * H2 + n] = 0.f;
    group_barrier(bt, 32);

    for (int t = 0; t < Tt; t++) {
        const float* hp = (t & 1) ? hb1 : hb0;
        float* hn = (t & 1) ? hb0 : hb1;

        ull a01[4], a23[4];
#pragma unroll
        for (int u = 0; u < 4; u++) {
            const float* gp = g_big + ((size_t)(b0 + u) * Tt + t) * G8 + n;
            a01[u] = pk2(gp[0], gp[H2]);
            a23[u] = pk2(gp[2 * H2], gp[3 * H2]);
        }

#pragma unroll
        for (int c = 0; c < 4; c++) {
            // stage chunk: 64 rows x 128 k, dup'd
            {
                int r = tid >> 5;            // 0..7 base row (8 rows per pass x 8 passes)
                int q = tid & 31;            // float4 index within 128-k row
#pragma unroll
                for (int p = 0; p < 8; p++) {
                    int row = r + p * 8;
                    float4 v = *(const float4*)(hp + (size_t)(bt * 64 + row) * H2 + c * 128 + q * 4);
                    float4* hdst = (float4*)(Hd + (size_t)row * 128);
                    hdst[2 * q]     = make_float4(v.x, v.x, v.y, v.y);
                    hdst[2 * q + 1] = make_float4(v.z, v.z, v.w, v.w);
                }
            }
            __syncthreads();
            const ull* hrow = (const ull*)Hd + (size_t)(wg * 8 + half * 4) * 128;
            const float* wrow = Ws + (size_t)c * 128 * 64 + nl * 4;
#pragma unroll 8
            for (int k = 0; k < 128; k++) {
                ulonglong2 wv = *(const ulonglong2*)(wrow + k * 64);
                ull h0 = hrow[k];
                ull h1 = hrow[128 + k];
                ull h2 = hrow[256 + k];
                ull h3 = hrow[384 + k];
                fma2(a01[0], h0, wv.x); fma2(a23[0], h0, wv.y);
                fma2(a01[1], h1, wv.x); fma2(a23[1], h1, wv.y);
                fma2(a01[2], h2, wv.x); fma2(a23[2], h2, wv.y);
                fma2(a01[3], h3, wv.x); fma2(a23[3], h3, wv.y);
            }
            __syncthreads();
        }
#pragma unroll
        for (int u = 0; u < 4; u++) {
            float2 p01 = up2(a01[u]);
            float2 p23 = up2(a23[u]);
            float ig = sigf(p01.x), fg = sigf(p01.y);
            float gg = tanhf(p23.x), og = sigf(p23.y);
            c_reg[u] = fg * c_reg[u] + ig * gg;
            float h = og * tanhf(c_reg[u]);
            hn[(size_t)(b0 + u) * H2 + n] = h;   // t=127 -> hb0 = hT
        }
        if (t < Tt - 1) group_barrier(bt, 32);
    }
}

// ---------------- emissions + CRF (single block) ------------------------------
__global__ void __launch_bounds__(256) crf_kernel(
    const int* __restrict__ y,
    const float* __restrict__ lin_w, const float* __restrict__ lin_b,
    const float* __restrict__ cstart, const float* __restrict__ cend,
    const float* __restrict__ ctrans, float* __restrict__ out)
{
    __shared__ float pool[NC * H2];
    __shared__ float e[Bq][NC];
    int tid = threadIdx.x;

    for (int idx = tid; idx < NC * H2 / 4; idx += 256)
        ((float4*)pool)[idx] = ((const float4*)lin_w)[idx];
    __syncthreads();
    {
        const float* hrow = &g_hs[0][tid][0];
        float acc[NC];
#pragma unroll
        for (int c = 0; c < NC; c++) acc[c] = lin_b[c];
        for (int k = 0; k < H2; k += 4) {
            float4 hv = *(const float4*)(hrow + k);
#pragma unroll
            for (int c = 0; c < NC; c++) {
                const float* wr = pool + c * H2 + k;
                acc[c] += hv.x * wr[0] + hv.y * wr[1] + hv.z * wr[2] + hv.w * wr[3];
            }
        }
#pragma unroll
        for (int c = 0; c < NC; c++) e[tid][c] = acc[c];
    }
    __syncthreads();
    if (tid < NC * NC) pool[tid] = ctrans[tid];
    __syncthreads();
    float* tr = pool;
    float* alpha = pool + 256;
    float* alpha2 = pool + 288;
    if (tid < NC) alpha[tid] = cstart[tid] + e[0][tid];
    __syncthreads();
    if (tid < 32) {
        for (int s = 1; s < Bq; s++) {
            if (tid < NC) {
                int j = tid;
                float m = -1e30f;
#pragma unroll
                for (int i = 0; i < NC; i++) m = fmaxf(m, alpha[i] + tr[i * NC + j]);
                float sum = 0.f;
#pragma unroll
                for (int i = 0; i < NC; i++) sum += expf(alpha[i] + tr[i * NC + j] - m);
                alpha2[j] = m + logf(sum) + e[s][j];
            }
            __syncwarp();
            if (tid < NC) alpha[tid] = alpha2[tid];
            __syncwarp();
        }
    }
    __syncthreads();
    if (tid == 0) {
        int yprev = y[0];
        float num = cstart[yprev] + e[0][yprev];
        for (int s = 1; s < Bq; s++) {
            int ys = y[s];
            num += tr[yprev * NC + ys] + e[s][ys];
            yprev = ys;
        }
        num += cend[yprev];
        float m = -1e30f;
        for (int i = 0; i < NC; i++) m = fmaxf(m, alpha[i] + cend[i]);
        float sum = 0.f;
        for (int i = 0; i < NC; i++) sum += expf(alpha[i] + cend[i] - m);
        out[0] = num - (m + logf(sum));
    }
}

// ---------------- launch ------------------------------------------------------
extern "C" void kernel_launch(void* const* d_in, const int* in_sizes, int n_in,
                              void* d_out, int out_size)
{
    const float* x      = (const float*)d_in[0];
    const int*   y      = (const int*)  d_in[1];
    const float* w_ih_f = (const float*)d_in[3];
    const float* w_hh_f = (const float*)d_in[4];
    const float* b_f    = (const float*)d_in[5];
    const float* w_ih_r = (const float*)d_in[6];
    const float* w_hh_r = (const float*)d_in[7];
    const float* b_r    = (const float*)d_in[8];
    const float* w_ih_s = (const float*)d_in[9];
    const float* w_hh_s = (const float*)d_in[10];
    const float* b_s    = (const float*)d_in[11];
    const float* lin_w  = (const float*)d_in[12];
    const float* lin_b  = (const float*)d_in[13];
    const float* cstart = (const float*)d_in[14];
    const float* cend   = (const float*)d_in[15];
    const float* ctrans = (const float*)d_in[16];
    float* out = (float*)d_out;

    float *gbig, *hcat, *wpf, *wpr, *wps;
    cudaGetSymbolAddress((void**)&gbig, g_big);
    cudaGetSymbolAddress((void**)&hcat, g_hcat);
    cudaGetSymbolAddress((void**)&wpf, g_wpf);
    cudaGetSymbolAddress((void**)&wpr, g_wpr);
    cudaGetSymbolAddress((void**)&wps, g_wps);

    cudaFuncSetAttribute(word_scan_kernel,
                         cudaFuncAttributeMaxDynamicSharedMemorySize, 196608);
    cudaFuncSetAttribute(sent_scan_kernel,
                         cudaFuncAttributeMaxDynamicSharedMemorySize, 196608);

    pack_whh<<<(4 * HH * HH + 255) / 256, 256>>>(w_hh_f, wpf, HH);
    pack_whh<<<(4 * HH * HH + 255) / 256, 256>>>(w_hh_r, wpr, HH);
    pack_whh<<<(4 * H2 * H2 + 255) / 256, 256>>>(w_hh_s, wps, H2);

    dim3 g1(G4 / 128, (Bq * Tt) / 128);
    gemm_tf32<<<g1, 256>>>(x, w_ih_f, b_f, gbig, Bq * Tt, G4, Ff);
    gemm_tf32<<<g1, 256>>>(x, w_ih_r, b_r, gbig + GXR_OFF, Bq * Tt, G4, Ff);

    word_scan_kernel<<<128, 256, 196608>>>();

    dim3 g2(G8 / 128, (Bq * Tt) / 128);
    gemm_tf32<<<g2, 256>>>(hcat, w_ih_s, b_s, gbig, Bq * Tt, G8, H2);

    sent_scan_kernel<<<128, 256, 196608>>>();

    crf_kernel<<<1, 256>>>(y, lin_w, lin_b, cstart, cend, ctrans, out);
}